// round 9
// baseline (speedup 1.0000x reference)
#include <cuda_runtime.h>
#include <cstdint>
#include <cstddef>
#include <math.h>

#define TT 512
#define BB 32
#define NBLK 128   // persistent recurrence grid size

// ---------------------------------------------------------------------------
// Device-global scratch (no allocation allowed)
// ---------------------------------------------------------------------------
__device__ float g_Xg[134217728];        // 16384 x 8192 input-proj gates (+biases), layout [b][t][8192]
__device__ float g_Y0[33554432];         // layer-0 output, layout (T,B,2048)
__device__ float g_ht[2 * 2 * 1024 * 32];// h state, [buf][d][u][b] (double buffered)
__device__ float g_cst[2 * 1024 * 32];   // c state, [d][u][b]
__device__ int   g_len[BB];
__device__ int   g_nact[TT];

// software grid barrier state (zero-initialized at module load)
__device__ volatile unsigned g_gen;
__device__ unsigned          g_count;

__device__ __forceinline__ void grid_sync()
{
    __syncthreads();
    if (threadIdx.x == 0) {
        __threadfence();
        unsigned gen = g_gen;
        if (atomicAdd(&g_count, 1u) == NBLK - 1) {
            g_count = 0;
            __threadfence();
            g_gen = gen + 1;
        } else {
            while (g_gen == gen) { }
        }
    }
    __syncthreads();
}

// ---------------------------------------------------------------------------
// Length extraction from mask (mask[b,t] = t >= len[b]); dtype-robust.
// Pass 1: uint8 nonzero + monotone check. Fallback: int32 view (also covers
// float32, since 1.0f is a nonzero 32-bit word).
// ---------------------------------------------------------------------------
__global__ void pk_lengths(const unsigned char* __restrict__ m8)
{
    __shared__ int slen[BB];
    int b = threadIdx.x;
    if (b < BB) {
        const int* m32 = (const int*)m8;
        int first1 = TT; bool ok = true;
        for (int t = 0; t < TT; ++t) {
            bool tv = (m8[b * TT + t] != 0);
            if (tv) { if (first1 == TT) first1 = t; }
            else if (first1 != TT) ok = false;   // non-monotone -> wrong dtype
        }
        unsigned bal = __ballot_sync(0xffffffffu, ok);
        if (bal != 0xffffffffu) {
            first1 = TT;
            for (int t = 0; t < TT; ++t) {
                if (m32[b * TT + t] != 0 && first1 == TT) first1 = t;
            }
        }
        slen[b] = first1;
        g_len[b] = first1;
    }
    __syncthreads();
    for (int s = threadIdx.x; s < TT; s += blockDim.x) {
        int c = 0;
        #pragma unroll
        for (int j = 0; j < BB; ++j) c += (slen[j] > s) ? 1 : 0;
        g_nact[s] = c;   // lens sorted descending -> active batches are prefix [0, nact)
    }
}

// ---------------------------------------------------------------------------
// Zero helpers
// ---------------------------------------------------------------------------
__global__ void pk_zero_y0()
{
    size_t n = 33554432ULL;
    size_t st = (size_t)gridDim.x * blockDim.x;
    for (size_t i = (size_t)blockIdx.x * blockDim.x + threadIdx.x; i < n; i += st)
        g_Y0[i] = 0.f;
}
__global__ void pk_zero_out(float* __restrict__ p, size_t n)
{
    size_t st = (size_t)gridDim.x * blockDim.x;
    for (size_t i = (size_t)blockIdx.x * blockDim.x + threadIdx.x; i < n; i += st)
        p[i] = 0.f;
}

// ---------------------------------------------------------------------------
// Input-projection GEMM:
//   Xg[(b*512+t)*8192 + n] = sum_k A[t][b][k] * W[n][k] + b1[n] + b2[n]
// A is (T,B,2048): x for layer 0, g_Y0 for layer 1 (use_y0).
// Tile 128 rows (consecutive t within one b) x 64 cols, BK=8, 256 threads,
// 8x4 microtile. Fully-invalid tiles (t0 >= len[b]) are skipped.
// ---------------------------------------------------------------------------
__global__ __launch_bounds__(256)
void pk_gemm(const float* __restrict__ Xin, int use_y0,
             const float* __restrict__ W,
             const float* __restrict__ b1, const float* __restrict__ b2)
{
    int rowTile = blockIdx.y;
    int b  = rowTile >> 2;
    int t0 = (rowTile & 3) << 7;
    if (t0 >= g_len[b]) return;
    int n0 = blockIdx.x << 6;

    const float* A = use_y0 ? g_Y0 : Xin;

    __shared__ float As[8][132];   // row stride 528B (16B multiple)
    __shared__ float Bs[8][68];    // row stride 272B (16B multiple)

    int tid = threadIdx.x;
    int ar = tid >> 1, ak = (tid & 1) << 2;   // loaders
    int tr = tid >> 4, tc = tid & 15;         // compute: 16x16 thread grid

    float acc[8][4];
    #pragma unroll
    for (int i = 0; i < 8; ++i)
        #pragma unroll
        for (int j = 0; j < 4; ++j) acc[i][j] = 0.f;

    for (int k0 = 0; k0 < 2048; k0 += 8) {
        float4 av = *(const float4*)(A + (size_t)(t0 + ar) * 65536 + (size_t)b * 2048 + k0 + ak);
        float4 bv = make_float4(0.f, 0.f, 0.f, 0.f);
        if (tid < 128)
            bv = *(const float4*)(W + (size_t)(n0 + ar) * 2048 + k0 + ak);
        __syncthreads();   // protect previous iteration's smem reads
        As[ak + 0][ar] = av.x; As[ak + 1][ar] = av.y;
        As[ak + 2][ar] = av.z; As[ak + 3][ar] = av.w;
        if (tid < 128) {
            Bs[ak + 0][ar] = bv.x; Bs[ak + 1][ar] = bv.y;
            Bs[ak + 2][ar] = bv.z; Bs[ak + 3][ar] = bv.w;
        }
        __syncthreads();

        #pragma unroll
        for (int kk = 0; kk < 8; ++kk) {
            float4 a0 = *(float4*)&As[kk][tr * 8];
            float4 a1 = *(float4*)&As[kk][tr * 8 + 4];
            float4 bq = *(float4*)&Bs[kk][tc * 4];
            float av8[8] = {a0.x, a0.y, a0.z, a0.w, a1.x, a1.y, a1.z, a1.w};
            float bv4[4] = {bq.x, bq.y, bq.z, bq.w};
            #pragma unroll
            for (int i = 0; i < 8; ++i)
                #pragma unroll
                for (int j = 0; j < 4; ++j)
                    acc[i][j] += av8[i] * bv4[j];
        }
    }

    float4 q1 = *(const float4*)(b1 + n0 + tc * 4);
    float4 q2 = *(const float4*)(b2 + n0 + tc * 4);
    float bs[4] = {q1.x + q2.x, q1.y + q2.y, q1.z + q2.z, q1.w + q2.w};

    #pragma unroll
    for (int i = 0; i < 8; ++i) {
        size_t row = (size_t)b * 512 + t0 + tr * 8 + i;
        float4 v = make_float4(acc[i][0] + bs[0], acc[i][1] + bs[1],
                               acc[i][2] + bs[2], acc[i][3] + bs[3]);
        *(float4*)(g_Xg + row * 8192 + n0 + tc * 4) = v;
    }
}

// ---------------------------------------------------------------------------
// Persistent recurrence kernel: one launch per layer runs all 512 steps for
// both directions, synchronizing the 128 resident blocks with a software
// grid barrier between steps. Prologue zeroes h/c; epilogue saves h_n/c_n.
// Block = (dir d, 16 units) -> 64 gate columns x 32 batches.
// ---------------------------------------------------------------------------
__global__ __launch_bounds__(256, 1)
void pk_recur(const float* __restrict__ Whh_l,
              float* __restrict__ outp, int use_out,
              float* __restrict__ out_final, int lidx0)
{
    __shared__ float Hs[32][32];      // h chunk [k][b]
    __shared__ float Ws[64][33];      // W chunk [col][k], padded
    __shared__ float Sg[32][68];      // gates  [b][col], padded
    __shared__ int   slen[32];

    int tid = threadIdx.x;
    int d  = blockIdx.x >> 6;
    int u0 = (blockIdx.x & 63) << 4;

    if (tid < 32) slen[tid] = g_len[tid];
    __syncthreads();

    // zero this block's h (both buffers) and c slices
    for (int r = tid; r < 512; r += 256) {
        int uu = r >> 5, b = r & 31;
        int ci = d * 32768 + (u0 + uu) * 32 + b;
        g_ht[ci] = 0.f; g_ht[65536 + ci] = 0.f; g_cst[ci] = 0.f;
    }
    grid_sync();

    int col  = tid & 63;                   // gate*16 + uu
    int gate = col >> 4, uu = col & 15;
    int b0   = (tid >> 6) << 3;
    int gcol = d * 4096 + gate * 1024 + u0 + uu;   // Xg column == Whh row

    for (int s = 0; s < TT; ++s) {
        int nact = g_nact[s];

        float acc[8];
        #pragma unroll
        for (int j = 0; j < 8; ++j) {
            int b = b0 + j;
            float v = 0.f;
            if (b < nact) {
                int t = d ? (slen[b] - 1 - s) : s;
                v = g_Xg[(size_t)(b * 512 + t) * 8192 + gcol];
            }
            acc[j] = v;
        }

        const float* hbuf = g_ht + (size_t)(s & 1) * 65536 + d * 32768;

        for (int k0 = 0; k0 < 1024; k0 += 32) {
            {   // load h chunk: 32 k x 32 b
                int kk = tid >> 3, b4 = (tid & 7) << 2;
                float4 hv = *(const float4*)(hbuf + (size_t)(k0 + kk) * 32 + b4);
                *(float4*)&Hs[kk][b4] = hv;
            }
            #pragma unroll
            for (int r = 0; r < 2; ++r) {   // load W chunk: 64 rows x 32 k
                int idx = tid + (r << 8);
                int row = idx >> 3, k4 = (idx & 7) << 2;
                int wrow = d * 4096 + (row >> 4) * 1024 + u0 + (row & 15);
                float4 wv = *(const float4*)(Whh_l + (size_t)wrow * 1024 + k0 + k4);
                Ws[row][k4 + 0] = wv.x; Ws[row][k4 + 1] = wv.y;
                Ws[row][k4 + 2] = wv.z; Ws[row][k4 + 3] = wv.w;
            }
            __syncthreads();
            if (b0 < nact) {
                #pragma unroll
                for (int kk = 0; kk < 32; ++kk) {
                    float w  = Ws[col][kk];
                    float4 h0 = *(float4*)&Hs[kk][b0];
                    float4 h1 = *(float4*)&Hs[kk][b0 + 4];
                    acc[0] += w * h0.x; acc[1] += w * h0.y;
                    acc[2] += w * h0.z; acc[3] += w * h0.w;
                    acc[4] += w * h1.x; acc[5] += w * h1.y;
                    acc[6] += w * h1.z; acc[7] += w * h1.w;
                }
            }
            __syncthreads();
        }

        #pragma unroll
        for (int j = 0; j < 8; ++j) Sg[b0 + j][col] = acc[j];
        __syncthreads();

        float* hw   = g_ht + (size_t)((s + 1) & 1) * 65536 + d * 32768;
        float* cbuf = g_cst + d * 32768;

        #pragma unroll
        for (int r = 0; r < 2; ++r) {
            int cid = tid + (r << 8);          // 512 cells = 16 units x 32 batches
            int cu = cid & 15, cb = cid >> 4;
            if (cb < nact) {
                float gi = Sg[cb][cu];
                float gf = Sg[cb][16 + cu];
                float gg = Sg[cb][32 + cu];
                float go = Sg[cb][48 + cu];
                float iv = 1.f / (1.f + expf(-gi));
                float fv = 1.f / (1.f + expf(-gf));
                float gv = tanhf(gg);
                float ov = 1.f / (1.f + expf(-go));
                int ci = (u0 + cu) * 32 + cb;
                float cn = fv * cbuf[ci] + iv * gv;
                float hn = ov * tanhf(cn);
                cbuf[ci] = cn;
                hw[ci]   = hn;
                float* yout = use_out ? outp : g_Y0;
                int t = d ? (slen[cb] - 1 - s) : s;
                yout[(size_t)t * 65536 + (size_t)cb * 2048 + d * 1024 + u0 + cu] = hn;
            }
        }
        grid_sync();
    }

    // epilogue: save final h/c for this block's units.
    // Final h for batch b lives in buffer (len[b] & 1) (last active write).
    for (int r = tid; r < 512; r += 256) {
        int uu2 = r >> 5, b = r & 31;
        int buf = slen[b] & 1;
        int ci  = d * 32768 + (u0 + uu2) * 32 + b;
        float hv = g_ht[(size_t)buf * 65536 + ci];
        float cv = g_cst[ci];
        size_t o = (size_t)(lidx0 + d) * 32768 + (size_t)b * 1024 + (u0 + uu2);
        out_final[33554432ULL + o]          = hv;
        out_final[33554432ULL + 131072 + o] = cv;
    }
}

// ---------------------------------------------------------------------------
// Launch: 7 graph nodes total (no per-step launches -> no graph upload buffer)
// ---------------------------------------------------------------------------
extern "C" void kernel_launch(void* const* d_in, const int* in_sizes, int n_in,
                              void* d_out, int out_size)
{
    const float* x            = (const float*)d_in[0];
    const unsigned char* mask = (const unsigned char*)d_in[1];
    const float* Wih          = (const float*)d_in[2];
    const float* Whh          = (const float*)d_in[3];
    const float* bih          = (const float*)d_in[4];
    const float* bhh          = (const float*)d_in[5];
    float* out = (float*)d_out;

    pk_lengths<<<1, 256>>>(mask);
    pk_zero_y0<<<2048, 256>>>();
    pk_zero_out<<<2048, 256>>>(out, (size_t)33554432ULL);

    for (int l = 0; l < 2; ++l) {
        pk_gemm<<<dim3(128, 128), 256>>>(
            x, l,
            Wih + (size_t)l * 2 * 4096 * 2048,
            bih + (size_t)l * 8192,
            bhh + (size_t)l * 8192);
        const float* whl = Whh + (size_t)l * 2 * 4096 * 1024;
        pk_recur<<<NBLK, 256>>>(whl, out, l, out, l * 2);
    }
}

// round 11
// speedup vs baseline: 1.3356x; 1.3356x over previous
#include <cuda_runtime.h>
#include <cstdint>
#include <cstddef>
#include <math.h>

#define TT 512
#define BB 32
#define NBLK 128   // persistent recurrence grid size

// ---------------------------------------------------------------------------
// Device-global scratch (no allocation allowed)
// ---------------------------------------------------------------------------
__device__ float g_Xg[134217728];        // 16384 x 8192 input-proj gates (+biases), layout [b][t][8192]
__device__ float g_Y0[33554432];         // layer-0 output, layout (T,B,2048)
__device__ float g_ht[2 * 2 * 1024 * 32];// h state, [buf][d][u][b] (double buffered)
__device__ float g_cst[2 * 1024 * 32];   // c state, [d][u][b]
__device__ int   g_len[BB];
__device__ int   g_nact[TT];

// software grid barrier state (zero-initialized at module load)
__device__ volatile unsigned g_gen;
__device__ unsigned          g_count;

__device__ __forceinline__ void grid_sync()
{
    __syncthreads();
    if (threadIdx.x == 0) {
        __threadfence();
        unsigned gen = g_gen;
        if (atomicAdd(&g_count, 1u) == NBLK - 1) {
            g_count = 0;
            __threadfence();
            g_gen = gen + 1;
        } else {
            while (g_gen == gen) { }
        }
    }
    __syncthreads();
}

// ---------------------------------------------------------------------------
// Length extraction from mask (mask[b,t] = t >= len[b]); dtype-robust.
// ---------------------------------------------------------------------------
__global__ void pk_lengths(const unsigned char* __restrict__ m8)
{
    __shared__ int slen[BB];
    int b = threadIdx.x;
    if (b < BB) {
        const int* m32 = (const int*)m8;
        int first1 = TT; bool ok = true;
        for (int t = 0; t < TT; ++t) {
            bool tv = (m8[b * TT + t] != 0);
            if (tv) { if (first1 == TT) first1 = t; }
            else if (first1 != TT) ok = false;   // non-monotone -> wrong dtype
        }
        unsigned bal = __ballot_sync(0xffffffffu, ok);
        if (bal != 0xffffffffu) {
            first1 = TT;
            for (int t = 0; t < TT; ++t) {
                if (m32[b * TT + t] != 0 && first1 == TT) first1 = t;
            }
        }
        slen[b] = first1;
        g_len[b] = first1;
    }
    __syncthreads();
    for (int s = threadIdx.x; s < TT; s += blockDim.x) {
        int c = 0;
        #pragma unroll
        for (int j = 0; j < BB; ++j) c += (slen[j] > s) ? 1 : 0;
        g_nact[s] = c;   // lens sorted descending -> active batches are prefix [0, nact)
    }
}

// ---------------------------------------------------------------------------
// Zero helpers
// ---------------------------------------------------------------------------
__global__ void pk_zero_y0()
{
    size_t n = 33554432ULL;
    size_t st = (size_t)gridDim.x * blockDim.x;
    for (size_t i = (size_t)blockIdx.x * blockDim.x + threadIdx.x; i < n; i += st)
        g_Y0[i] = 0.f;
}
__global__ void pk_zero_out(float* __restrict__ p, size_t n)
{
    size_t st = (size_t)gridDim.x * blockDim.x;
    for (size_t i = (size_t)blockIdx.x * blockDim.x + threadIdx.x; i < n; i += st)
        p[i] = 0.f;
}

// ---------------------------------------------------------------------------
// Input-projection GEMM:
//   Xg[(b*512+t)*8192 + n] = sum_k A[t][b][k] * W[n][k] + b1[n] + b2[n]
// Tile 128 rows (consecutive t within one b) x 128 cols, BK=8, 256 threads,
// 8x8 microtile with 4+64 fragment split (conflict-free LDS), register-staged
// gmem prefetch. Fully-invalid tiles (t0 >= len[b]) are skipped.
// ---------------------------------------------------------------------------
__global__ __launch_bounds__(256)
void pk_gemm(const float* __restrict__ Xin, int use_y0,
             const float* __restrict__ W,
             const float* __restrict__ b1, const float* __restrict__ b2)
{
    int rowTile = blockIdx.y;
    int b  = rowTile >> 2;
    int t0 = (rowTile & 3) << 7;
    if (t0 >= g_len[b]) return;
    int n0 = blockIdx.x << 7;

    const float* A = use_y0 ? g_Y0 : Xin;

    __shared__ float As[8][132];
    __shared__ float Bs[8][132];

    int tid = threadIdx.x;
    int lr = tid >> 1, lk = (tid & 1) << 2;   // loader: row 0..127, k 0/4
    int tr = tid >> 4, tc = tid & 15;         // 16x16 compute grid

    const float* Aptr = A + (size_t)(t0 + lr) * 65536 + (size_t)b * 2048 + lk;
    const float* Wptr = W + (size_t)(n0 + lr) * 2048 + lk;

    float4 av = *(const float4*)(Aptr);
    float4 bv = *(const float4*)(Wptr);

    float acc[8][8];
    #pragma unroll
    for (int i = 0; i < 8; ++i)
        #pragma unroll
        for (int j = 0; j < 8; ++j) acc[i][j] = 0.f;

    for (int k0 = 0; k0 < 2048; k0 += 8) {
        __syncthreads();   // previous iteration's smem reads done
        As[lk + 0][lr] = av.x; As[lk + 1][lr] = av.y;
        As[lk + 2][lr] = av.z; As[lk + 3][lr] = av.w;
        Bs[lk + 0][lr] = bv.x; Bs[lk + 1][lr] = bv.y;
        Bs[lk + 2][lr] = bv.z; Bs[lk + 3][lr] = bv.w;
        __syncthreads();

        if (k0 + 8 < 2048) {   // stage next tile (overlaps compute)
            av = *(const float4*)(Aptr + k0 + 8);
            bv = *(const float4*)(Wptr + k0 + 8);
        }

        #pragma unroll
        for (int kk = 0; kk < 8; ++kk) {
            float4 a0 = *(float4*)&As[kk][tr * 4];
            float4 a1 = *(float4*)&As[kk][64 + tr * 4];
            float4 c0 = *(float4*)&Bs[kk][tc * 4];
            float4 c1 = *(float4*)&Bs[kk][64 + tc * 4];
            float ar8[8] = {a0.x, a0.y, a0.z, a0.w, a1.x, a1.y, a1.z, a1.w};
            float br8[8] = {c0.x, c0.y, c0.z, c0.w, c1.x, c1.y, c1.z, c1.w};
            #pragma unroll
            for (int i = 0; i < 8; ++i)
                #pragma unroll
                for (int j = 0; j < 8; ++j)
                    acc[i][j] += ar8[i] * br8[j];
        }
    }

    float4 q1a = *(const float4*)(b1 + n0 + tc * 4);
    float4 q2a = *(const float4*)(b2 + n0 + tc * 4);
    float4 q1b = *(const float4*)(b1 + n0 + 64 + tc * 4);
    float4 q2b = *(const float4*)(b2 + n0 + 64 + tc * 4);
    float bs[8] = {q1a.x + q2a.x, q1a.y + q2a.y, q1a.z + q2a.z, q1a.w + q2a.w,
                   q1b.x + q2b.x, q1b.y + q2b.y, q1b.z + q2b.z, q1b.w + q2b.w};

    #pragma unroll
    for (int i = 0; i < 8; ++i) {
        int r = (i < 4) ? (tr * 4 + i) : (64 + tr * 4 + i - 4);
        size_t row = (size_t)b * 512 + t0 + r;
        float4 v0 = make_float4(acc[i][0] + bs[0], acc[i][1] + bs[1],
                                acc[i][2] + bs[2], acc[i][3] + bs[3]);
        float4 v1 = make_float4(acc[i][4] + bs[4], acc[i][5] + bs[5],
                                acc[i][6] + bs[6], acc[i][7] + bs[7]);
        *(float4*)(g_Xg + row * 8192 + n0 + tc * 4)      = v0;
        *(float4*)(g_Xg + row * 8192 + n0 + 64 + tc * 4) = v1;
    }
}

// ---------------------------------------------------------------------------
// Persistent recurrence kernel: one launch per layer runs all 512 steps for
// both directions (software grid barrier between steps).
// Block = (dir d, 16 units) -> 64 gate columns x 32 batches.
// Thread = 2 cols (cp, cp+32) x 4 batches; chunk loads software-pipelined.
// ---------------------------------------------------------------------------
__global__ __launch_bounds__(256, 1)
void pk_recur(const float* __restrict__ Whh_l,
              float* __restrict__ outp, int use_out,
              float* __restrict__ out_final, int lidx0)
{
    __shared__ float Hs[32][32];      // h chunk [k][b]
    __shared__ float Ws[64][33];      // W chunk [col][k], padded (conflict-free)
    __shared__ float Sg[32][68];      // gates  [b][col], padded
    __shared__ int   slen[32];

    int tid = threadIdx.x;
    int d  = blockIdx.x >> 6;
    int u0 = (blockIdx.x & 63) << 4;

    if (tid < 32) slen[tid] = g_len[tid];
    __syncthreads();

    // zero this block's h (both buffers) and c slices
    for (int r = tid; r < 512; r += 256) {
        int uu = r >> 5, b = r & 31;
        int ci = d * 32768 + (u0 + uu) * 32 + b;
        g_ht[ci] = 0.f; g_ht[65536 + ci] = 0.f; g_cst[ci] = 0.f;
    }
    grid_sync();

    // compute mapping: thread = (cp, bg): cols cp & cp+32, batches bg*4..+3
    int cp = tid & 31;
    int bg = tid >> 5;          // warp-uniform
    int b0 = bg << 2;
    int g0 = cp >> 4,        uu0 = cp & 15;         // col cp
    int g1 = (cp + 32) >> 4, uu1 = (cp + 32) & 15;  // col cp+32
    int gcol0 = d * 4096 + g0 * 1024 + u0 + uu0;
    int gcol1 = d * 4096 + g1 * 1024 + u0 + uu1;

    // loader mapping
    int kk_l = tid >> 3, b4 = (tid & 7) << 2;       // Hs: [kk_l][b4..b4+3]
    int row0 = tid >> 3, row1 = 32 + (tid >> 3);    // Ws rows
    int k4   = (tid & 7) << 2;
    int wr0  = d * 4096 + (row0 >> 4) * 1024 + u0 + (row0 & 15);
    int wr1  = d * 4096 + (row1 >> 4) * 1024 + u0 + (row1 & 15);
    const float* wp0 = Whh_l + (size_t)wr0 * 1024 + k4;
    const float* wp1 = Whh_l + (size_t)wr1 * 1024 + k4;

    for (int s = 0; s < TT; ++s) {
        int nact = g_nact[s];

        // Xg gather (issues early; overlaps chunk-0 staging)
        float acc0[4], acc1[4];
        #pragma unroll
        for (int j = 0; j < 4; ++j) {
            int b = b0 + j;
            float v0 = 0.f, v1 = 0.f;
            if (b < nact) {
                int t = d ? (slen[b] - 1 - s) : s;
                size_t rbase = (size_t)(b * 512 + t) * 8192;
                v0 = g_Xg[rbase + gcol0];
                v1 = g_Xg[rbase + gcol1];
            }
            acc0[j] = v0; acc1[j] = v1;
        }

        const float* hbuf = g_ht + (size_t)(s & 1) * 65536 + d * 32768;

        // stage chunk 0
        float4 hv  = *(const float4*)(hbuf + (size_t)kk_l * 32 + b4);
        float4 wv0 = *(const float4*)(wp0);
        float4 wv1 = *(const float4*)(wp1);

        for (int k0 = 0; k0 < 1024; k0 += 32) {
            __syncthreads();   // previous chunk's smem reads done
            *(float4*)&Hs[kk_l][b4] = hv;
            Ws[row0][k4 + 0] = wv0.x; Ws[row0][k4 + 1] = wv0.y;
            Ws[row0][k4 + 2] = wv0.z; Ws[row0][k4 + 3] = wv0.w;
            Ws[row1][k4 + 0] = wv1.x; Ws[row1][k4 + 1] = wv1.y;
            Ws[row1][k4 + 2] = wv1.z; Ws[row1][k4 + 3] = wv1.w;
            __syncthreads();

            int k0n = k0 + 32;
            if (k0n < 1024) {   // stage next chunk (overlaps compute)
                hv  = *(const float4*)(hbuf + (size_t)(k0n + kk_l) * 32 + b4);
                wv0 = *(const float4*)(wp0 + k0n);
                wv1 = *(const float4*)(wp1 + k0n);
            }

            if (b0 < nact) {
                #pragma unroll
                for (int kk = 0; kk < 32; ++kk) {
                    float w0 = Ws[cp][kk];
                    float w1 = Ws[cp + 32][kk];
                    float4 h = *(float4*)&Hs[kk][b0];
                    acc0[0] += w0 * h.x; acc0[1] += w0 * h.y;
                    acc0[2] += w0 * h.z; acc0[3] += w0 * h.w;
                    acc1[0] += w1 * h.x; acc1[1] += w1 * h.y;
                    acc1[2] += w1 * h.z; acc1[3] += w1 * h.w;
                }
            }
        }
        __syncthreads();

        #pragma unroll
        for (int j = 0; j < 4; ++j) {
            Sg[b0 + j][cp]      = acc0[j];
            Sg[b0 + j][cp + 32] = acc1[j];
        }
        __syncthreads();

        float* hw   = g_ht + (size_t)((s + 1) & 1) * 65536 + d * 32768;
        float* cbuf = g_cst + d * 32768;

        #pragma unroll
        for (int r = 0; r < 2; ++r) {
            int cid = tid + (r << 8);          // 512 cells = 16 units x 32 batches
            int cu = cid & 15, cb = cid >> 4;
            if (cb < nact) {
                float gi = Sg[cb][cu];
                float gf = Sg[cb][16 + cu];
                float gg = Sg[cb][32 + cu];
                float go = Sg[cb][48 + cu];
                float iv = 1.f / (1.f + expf(-gi));
                float fv = 1.f / (1.f + expf(-gf));
                float gv = tanhf(gg);
                float ov = 1.f / (1.f + expf(-go));
                int ci = (u0 + cu) * 32 + cb;
                float cn = fv * cbuf[ci] + iv * gv;
                float hn = ov * tanhf(cn);
                cbuf[ci] = cn;
                hw[ci]   = hn;
                float* yout = use_out ? outp : g_Y0;
                int t = d ? (slen[cb] - 1 - s) : s;
                yout[(size_t)t * 65536 + (size_t)cb * 2048 + d * 1024 + u0 + cu] = hn;
            }
        }
        grid_sync();
    }

    // epilogue: save final h/c. Final h for batch b is in buffer (len[b] & 1).
    for (int r = tid; r < 512; r += 256) {
        int uu2 = r >> 5, b = r & 31;
        int buf = slen[b] & 1;
        int ci  = d * 32768 + (u0 + uu2) * 32 + b;
        float hv2 = g_ht[(size_t)buf * 65536 + ci];
        float cv2 = g_cst[ci];
        size_t o = (size_t)(lidx0 + d) * 32768 + (size_t)b * 1024 + (u0 + uu2);
        out_final[33554432ULL + o]          = hv2;
        out_final[33554432ULL + 131072 + o] = cv2;
    }
}

// ---------------------------------------------------------------------------
// Launch: 7 graph nodes total
// ---------------------------------------------------------------------------
extern "C" void kernel_launch(void* const* d_in, const int* in_sizes, int n_in,
                              void* d_out, int out_size)
{
    const float* x            = (const float*)d_in[0];
    const unsigned char* mask = (const unsigned char*)d_in[1];
    const float* Wih          = (const float*)d_in[2];
    const float* Whh          = (const float*)d_in[3];
    const float* bih          = (const float*)d_in[4];
    const float* bhh          = (const float*)d_in[5];
    float* out = (float*)d_out;

    pk_lengths<<<1, 256>>>(mask);
    pk_zero_y0<<<2048, 256>>>();
    pk_zero_out<<<2048, 256>>>(out, (size_t)33554432ULL);

    for (int l = 0; l < 2; ++l) {
        pk_gemm<<<dim3(64, 128), 256>>>(
            x, l,
            Wih + (size_t)l * 2 * 4096 * 2048,
            bih + (size_t)l * 8192,
            bhh + (size_t)l * 8192);
        const float* whl = Whh + (size_t)l * 2 * 4096 * 1024;
        pk_recur<<<NBLK, 256>>>(whl, out, l, out, l * 2);
    }
}